// round 16
// baseline (speedup 1.0000x reference)
#include <cuda_runtime.h>
#include <cuda_fp16.h>
#include <math.h>
#include <stdint.h>

#define BB 32
#define SS 4096
#define VD 512
#define HD 512
#define QD 512
#define CTX_SIZE (BB*VD)
#define CSPLIT 64

// -------- scratch (no allocation allowed) --------
__device__ float  g_qp[BB*HD];
__device__ float  g_scores[BB*SS];
__device__ __half g_WkT[HD*VD];            // [h][v] fp16 (B operand)
__device__ __half g_Vh[(size_t)BB*SS*VD];  // fp16 copy of value (spilled by score)

// ---------------- helpers ----------------
__device__ __forceinline__ uint32_t smem_u32(const void* p) {
    uint32_t a;
    asm("{ .reg .u64 t; cvta.to.shared.u64 t, %1; cvt.u32.u64 %0, t; }"
        : "=r"(a) : "l"(p));
    return a;
}
__device__ __forceinline__ void ldsm4(uint32_t* r, uint32_t addr) {
    asm volatile("ldmatrix.sync.aligned.m8n8.x4.shared.b16 {%0,%1,%2,%3}, [%4];"
        : "=r"(r[0]), "=r"(r[1]), "=r"(r[2]), "=r"(r[3]) : "r"(addr));
}
__device__ __forceinline__ void mma16816(float* d, const uint32_t* a, const uint32_t* b) {
    asm volatile("mma.sync.aligned.m16n8k16.row.col.f32.f16.f16.f32 "
        "{%0,%1,%2,%3}, {%4,%5,%6,%7}, {%8,%9}, {%0,%1,%2,%3};"
        : "+f"(d[0]), "+f"(d[1]), "+f"(d[2]), "+f"(d[3])
        : "r"(a[0]), "r"(a[1]), "r"(a[2]), "r"(a[3]), "r"(b[0]), "r"(b[1]));
}
__device__ __forceinline__ float tanha(float x) {
    float y;
    asm("tanh.approx.f32 %0, %1;" : "=f"(y) : "f"(x));
    return y;
}
__device__ __forceinline__ void cp16(uint32_t dst, const void* src) {
    asm volatile("cp.async.cg.shared.global [%0], [%1], 16;"
                 :: "r"(dst), "l"(src) : "memory");
}
#define CP_COMMIT() asm volatile("cp.async.commit_group;" ::: "memory")
#define CP_WAIT(n)  asm volatile("cp.async.wait_group %0;" :: "n"(n) : "memory")

// ---------------- Kernel 1: fused prep ----------------
__global__ __launch_bounds__(512)
void prep_kernel(const float* __restrict__ query,
                 const float* __restrict__ Wq,
                 const float* __restrict__ bq,
                 const float* __restrict__ Wk,
                 float* __restrict__ ctx) {
    const int blk = blockIdx.x;
    if (blk < 256) {
        __shared__ float tile[32][33];
        const int tv = blk & 15, th = blk >> 4;
        const int c  = threadIdx.x & 31;
        const int r0 = threadIdx.x >> 5;       // 0..15
        #pragma unroll
        for (int rr = 0; rr < 2; rr++) {
            int r = r0 + rr*16;
            tile[r][c] = Wk[(size_t)(tv*32 + r)*HD + th*32 + c];
        }
        __syncthreads();
        #pragma unroll
        for (int rr = 0; rr < 2; rr++) {
            int r2 = r0 + rr*16;
            g_WkT[(size_t)(th*32 + r2)*VD + tv*32 + c] =
                __float2half_rn(tile[c][r2]);
        }
    } else if (blk < 288) {
        int b = blk - 256;
        int h = threadIdx.x;
        __shared__ float qs[QD];
        qs[h] = query[b*QD + h];
        __syncthreads();
        float acc = 0.f;
        #pragma unroll 8
        for (int v = 0; v < QD; v++) acc += qs[v] * Wq[v*HD + h];
        g_qp[b*HD + h] = acc + bq[h];
    } else {
        ctx[(blk - 288)*512 + threadIdx.x] = 0.f;
    }
}

// ---------------- Kernel 2: mma.sync score GEMM (R12 configuration) ----------
#define APAD 520
#define OFF_A   0
#define OFF_B   133120
#define OFF_QP  199680
#define OFF_WO  201728
#define OFF_RED 203776
#define OFF_S0  204288
#define CHUNK_B 8192
#define SMEM_TOTAL (204288 + 3*CHUNK_B)

__device__ __forceinline__ void prefetch_b64(uint32_t bbase, int t, int tid) {
    const __half* src = g_WkT + (size_t)t * 64 * VD;
    #pragma unroll
    for (int it = 0; it < 16; it++) {
        int i = tid + it*256;
        int n = i >> 6;
        int g = i & 63;
        cp16(bbase + (uint32_t)(n*APAD + g*8)*2, src + (size_t)n*VD + g*8);
    }
}

__device__ __forceinline__ void issue_chunk(uint32_t sb, const float* vrow0,
                                            int c, int tid) {
    const float* src = vrow0 + c*16;
    #pragma unroll
    for (int j = 0; j < 2; j++) {
        int s = tid + j*256;          // 0..511 segments of 16B
        int r = s >> 2, p = s & 3;
        cp16(sb + (uint32_t)s*16, src + (size_t)r*VD + p*4);
    }
}

__device__ __forceinline__ void convert_chunk(const float* S, __half* As,
                                              int c, int tid) {
    #pragma unroll
    for (int j = 0; j < 2; j++) {
        int q = tid + j*256;          // float4 id 0..511
        int r = q >> 2, c4 = q & 3;
        float4 f = *(const float4*)(S + q*4);
        __half2 h0 = __floats2half2_rn(f.x, f.y);
        __half2 h1 = __floats2half2_rn(f.z, f.w);
        *(uint2*)(As + r*APAD + c*16 + c4*4) =
            make_uint2(*(uint32_t*)&h0, *(uint32_t*)&h1);
    }
}

// spill rows [t*16, t*16+16) of resident A (fp16) to g_Vh, streaming stores
__device__ __forceinline__ void spill_slab(const __half* As, __half* vh0,
                                           int t, int tid) {
    #pragma unroll
    for (int j = 0; j < 4; j++) {
        int q = tid + j*256;          // 0..1023
        int r = t*16 + (q >> 6);      // row
        int g = q & 63;               // uint4 within row
        uint4 u = *(const uint4*)(As + r*APAD + g*8);
        __stcs((uint4*)(vh0 + (size_t)r*VD + g*8), u);
    }
}

__device__ __forceinline__ void epilogue_tile(const float (&acc)[2][4][4], int t,
                                              int nw, int L,
                                              const float* qp_s, const float* wo_s,
                                              float* sp) {
    #pragma unroll
    for (int ni = 0; ni < 4; ni++) {
        const int hb = t*64 + nw*32 + ni*8 + 2*(L & 3);
        const float qp0 = qp_s[hb],   qp1 = qp_s[hb + 1];
        const float wo0 = wo_s[hb],   wo1 = wo_s[hb + 1];
        #pragma unroll
        for (int mi = 0; mi < 2; mi++) {
            float t0 = tanha(acc[mi][ni][0] + qp0);
            float t1 = tanha(acc[mi][ni][1] + qp1);
            float t2 = tanha(acc[mi][ni][2] + qp0);
            float t3 = tanha(acc[mi][ni][3] + qp1);
            sp[mi*2 + 0] += wo0*t0 + wo1*t1;
            sp[mi*2 + 1] += wo0*t2 + wo1*t3;
        }
    }
}

__global__ __launch_bounds__(256, 1)
void score_mma_kernel(const float* __restrict__ value,
                      const float* __restrict__ Wo,
                      const float* __restrict__ bo) {
    extern __shared__ char sm[];
    const uint32_t sbase = smem_u32(sm);
    const int tid = threadIdx.x;
    const int L   = tid & 31;
    const int wid = tid >> 5;
    const int mw  = wid & 3;
    const int nw  = wid >> 2;
    const int b   = blockIdx.x >> 5;
    const size_t row0 = (size_t)blockIdx.x * 128;

    __half* As  = (__half*)(sm + OFF_A);
    float* qp_s = (float*)(sm + OFF_QP);
    float* wo_s = (float*)(sm + OFF_WO);
    float* red  = (float*)(sm + OFF_RED);
    const float* vrow0 = value + row0 * VD;
    __half* vh0 = g_Vh + row0 * VD;

    prefetch_b64(sbase + OFF_B, 0, tid);
    CP_COMMIT();
    issue_chunk(sbase + OFF_S0 + 0*CHUNK_B, vrow0, 0, tid);
    CP_COMMIT();
    issue_chunk(sbase + OFF_S0 + 1*CHUNK_B, vrow0, 1, tid);
    CP_COMMIT();

    for (int i = tid; i < HD; i += 256) {
        qp_s[i] = g_qp[b*HD + i];
        wo_s[i] = Wo[i];
    }
    if (tid < 128) red[tid] = 0.f;

    const uint32_t aAddr = sbase + OFF_A +
        (uint32_t)(((mw*32 + (L & 15))*APAD + (L >> 4)*8) * 2);
    const uint32_t bAddr = sbase + OFF_B +
        (uint32_t)(((nw*32 + (L & 7) + ((L >> 4) << 3))*APAD + ((L >> 3) & 1)*8) * 2);

    float sp[4] = {0.f, 0.f, 0.f, 0.f};

    // ================= tile 0: chunked A pipeline =================
    float acc[2][4][4];
    #pragma unroll
    for (int mi = 0; mi < 2; mi++)
        #pragma unroll
        for (int ni = 0; ni < 4; ni++)
            #pragma unroll
            for (int j = 0; j < 4; j++) acc[mi][ni][j] = 0.f;

    for (int c = 0; c < 32; c++) {
        if (c <= 29) {
            int cn = c + 2;
            issue_chunk(sbase + OFF_S0 + (cn % 3)*CHUNK_B, vrow0, cn, tid);
            CP_COMMIT();
            CP_WAIT(2);
        } else if (c == 30) {
            CP_WAIT(1);
        } else {
            CP_WAIT(0);
        }
        __syncthreads();
        convert_chunk((const float*)(sm + OFF_S0 + (c % 3)*CHUNK_B), As, c, tid);
        __syncthreads();

        const uint32_t kb = (uint32_t)c * 32;
        uint32_t a0[4], a1[4], b0[4], b1[4];
        ldsm4(a0, aAddr + kb);
        ldsm4(a1, aAddr + 16*APAD*2 + kb);
        ldsm4(b0, bAddr + kb);
        ldsm4(b1, bAddr + 16*APAD*2 + kb);
        mma16816(acc[0][0], a0, b0 + 0);
        mma16816(acc[0][1], a0, b0 + 2);
        mma16816(acc[0][2], a0, b1 + 0);
        mma16816(acc[0][3], a0, b1 + 2);
        mma16816(acc[1][0], a1, b0 + 0);
        mma16816(acc[1][1], a1, b0 + 2);
        mma16816(acc[1][2], a1, b1 + 0);
        mma16816(acc[1][3], a1, b1 + 2);
    }

    __syncthreads();                  // all warps done reading B0
    prefetch_b64(sbase + OFF_B, 1, tid);
    CP_COMMIT();
    spill_slab(As, vh0, 0, tid);
    epilogue_tile(acc, 0, nw, L, qp_s, wo_s, sp);

    // ================= tiles 1..7: A resident, pipelined k-loop ===========
    for (int t = 1; t < 8; t++) {
        CP_WAIT(0);
        __syncthreads();

        #pragma unroll
        for (int mi = 0; mi < 2; mi++)
            #pragma unroll
            for (int ni = 0; ni < 4; ni++)
                #pragma unroll
                for (int j = 0; j < 4; j++) acc[mi][ni][j] = 0.f;

        uint32_t fA0[2][4], fA1[2][4], fB0[2][4], fB1[2][4];
        ldsm4(fA0[0], aAddr);
        ldsm4(fA1[0], aAddr + 16*APAD*2);
        ldsm4(fB0[0], bAddr);
        ldsm4(fB1[0], bAddr + 16*APAD*2);

        #pragma unroll
        for (int ks = 0; ks < 32; ks++) {
            const int cur = ks & 1, nxt = cur ^ 1;
            if (ks < 31) {
                const uint32_t kb = (uint32_t)(ks + 1) * 32;
                ldsm4(fA0[nxt], aAddr + kb);
                ldsm4(fA1[nxt], aAddr + 16*APAD*2 + kb);
                ldsm4(fB0[nxt], bAddr + kb);
                ldsm4(fB1[nxt], bAddr + 16*APAD*2 + kb);
            }
            mma16816(acc[0][0], fA0[cur], fB0[cur] + 0);
            mma16816(acc[0][1], fA0[cur], fB0[cur] + 2);
            mma16816(acc[0][2], fA0[cur], fB1[cur] + 0);
            mma16816(acc[0][3], fA0[cur], fB1[cur] + 2);
            mma16816(acc[1][0], fA1[cur], fB0[cur] + 0);
            mma16816(acc[1][1], fA1[cur], fB0[cur] + 2);
            mma16816(acc[1][2], fA1[cur], fB1[cur] + 0);
            mma16816(acc[1][3], fA1[cur], fB1[cur] + 2);
        }

        __syncthreads();
        if (t < 7) {
            prefetch_b64(sbase + OFF_B, t + 1, tid);
            CP_COMMIT();
        }
        spill_slab(As, vh0, t, tid);
        epilogue_tile(acc, t, nw, L, qp_s, wo_s, sp);
    }

    #pragma unroll
    for (int i = 0; i < 4; i++) {
        sp[i] += __shfl_xor_sync(0xffffffffu, sp[i], 1);
        sp[i] += __shfl_xor_sync(0xffffffffu, sp[i], 2);
    }
    if ((L & 3) == 0) {
        const int mr = mw*32 + (L >> 2);
        atomicAdd(&red[mr +  0], sp[0]);
        atomicAdd(&red[mr +  8], sp[1]);
        atomicAdd(&red[mr + 16], sp[2]);
        atomicAdd(&red[mr + 24], sp[3]);
    }
    __syncthreads();
    if (tid < 128)
        g_scores[row0 + tid] = red[tid] + bo[0];
}

// ---------------- Kernel 3: masked softmax ----------------
__global__ __launch_bounds__(512)
void softmax_kernel(const int* __restrict__ mask,
                    float* __restrict__ att_out) {
    const int b = blockIdx.x;
    const int tid = threadIdx.x;
    const int L = tid & 31, w = tid >> 5;
    __shared__ float sred[16];

    float v[8];
    float m = -3.0e38f;
    #pragma unroll
    for (int i = 0; i < 8; i++) {
        int s = tid + i*512;
        float sc = (mask[b*SS + s] != 0) ? g_scores[b*SS + s] : -1e9f;
        v[i] = sc;
        m = fmaxf(m, sc);
    }
    #pragma unroll
    for (int off = 16; off > 0; off >>= 1)
        m = fmaxf(m, __shfl_xor_sync(0xffffffffu, m, off));
    if (L == 0) sred[w] = m;
    __syncthreads();
    if (w == 0) {
        float x = (L < 16) ? sred[L] : -3.0e38f;
        #pragma unroll
        for (int off = 8; off > 0; off >>= 1)
            x = fmaxf(x, __shfl_xor_sync(0xffffffffu, x, off));
        if (L == 0) sred[0] = x;
    }
    __syncthreads();
    m = sred[0];
    __syncthreads();

    float sum = 0.f;
    #pragma unroll
    for (int i = 0; i < 8; i++) {
        v[i] = expf(v[i] - m);
        sum += v[i];
    }
    #pragma unroll
    for (int off = 16; off > 0; off >>= 1)
        sum += __shfl_xor_sync(0xffffffffu, sum, off);
    if (L == 0) sred[w] = sum;
    __syncthreads();
    if (w == 0) {
        float x = (L < 16) ? sred[L] : 0.f;
        #pragma unroll
        for (int off = 8; off > 0; off >>= 1)
            x += __shfl_xor_sync(0xffffffffu, x, off);
        if (L == 0) sred[0] = x;
    }
    __syncthreads();
    const float inv = 1.f / sred[0];

    #pragma unroll
    for (int i = 0; i < 8; i++)
        att_out[b*SS + tid + i*512] = v[i] * inv;
}

// ---------------- Kernel 4: ctx from fp16 value, 256 thr, split s-range -------
// Same per-thread access pattern as R12 (uint2 at column t*4, sequential rows);
// threads 0-127 cover s in [0,32), threads 128-255 cover s in [32,64).
__global__ __launch_bounds__(256)
void ctx_part_kernel(const float* __restrict__ att,
                     float* __restrict__ ctx) {
    __shared__ float atts[SS / CSPLIT];          // 64
    const int b  = blockIdx.y, sc = blockIdx.x;
    const int t  = threadIdx.x & 127;            // column group (4 halfs)
    const int sh = (threadIdx.x >> 7) * 32;      // s-range half: 0 or 32
    const int s0 = sc * (SS / CSPLIT);

    if (threadIdx.x < SS / CSPLIT)
        atts[threadIdx.x] = att[b*SS + s0 + threadIdx.x];
    __syncthreads();

    const __half* vb = g_Vh + ((size_t)(b*SS + s0 + sh))*VD + t*4;
    float ax = 0.f, ay = 0.f, az = 0.f, aw = 0.f;
    #pragma unroll 8
    for (int s = 0; s < 32; s++) {
        float a = atts[sh + s];
        uint2 u = *(const uint2*)(vb + (size_t)s*VD);
        float2 f01 = __half22float2(*(const __half2*)&u.x);
        float2 f23 = __half22float2(*(const __half2*)&u.y);
        ax = fmaf(a, f01.x, ax); ay = fmaf(a, f01.y, ay);
        az = fmaf(a, f23.x, az); aw = fmaf(a, f23.y, aw);
    }
    float* dst = ctx + b*VD + t*4;
    atomicAdd(dst + 0, ax);
    atomicAdd(dst + 1, ay);
    atomicAdd(dst + 2, az);
    atomicAdd(dst + 3, aw);
}

extern "C" void kernel_launch(void* const* d_in, const int* in_sizes, int n_in,
                              void* d_out, int out_size) {
    const float* query = (const float*)d_in[0];
    const float* value = (const float*)d_in[1];
    const int*   mask  = (const int*)d_in[2];   // bool promoted to int32
    const float* Wk    = (const float*)d_in[3];
    const float* Wq    = (const float*)d_in[4];
    const float* bq    = (const float*)d_in[5];
    const float* Wo    = (const float*)d_in[6];
    const float* bo    = (const float*)d_in[7];

    float* out = (float*)d_out;
    float* ctx = out;                 // [B, VD]
    float* att = out + CTX_SIZE;      // [B, S]

    prep_kernel<<<320, 512>>>(query, Wq, bq, Wk, ctx);

    cudaFuncSetAttribute(score_mma_kernel,
                         cudaFuncAttributeMaxDynamicSharedMemorySize, SMEM_TOTAL);
    score_mma_kernel<<<(BB*SS)/128, 256, SMEM_TOTAL>>>(value, Wo, bo);

    softmax_kernel<<<BB, 512>>>(mask, att);

    ctx_part_kernel<<<dim3(CSPLIT, BB), 256>>>(att, ctx);
}

// round 17
// speedup vs baseline: 1.0262x; 1.0262x over previous
#include <cuda_runtime.h>
#include <cuda_fp16.h>
#include <math.h>
#include <stdint.h>

#define BB 32
#define SS 4096
#define VD 512
#define HD 512
#define QD 512
#define CTX_SIZE (BB*VD)
#define CSPLIT 64

// -------- scratch (no allocation allowed) --------
__device__ float  g_qp[BB*HD];
__device__ float  g_scores[BB*SS];
__device__ __half g_WkT[HD*VD];            // [h][v] fp16 (B operand)
__device__ __half g_Vh[(size_t)BB*SS*VD];  // fp16 copy of value (spilled by score)

// ---------------- helpers ----------------
__device__ __forceinline__ uint32_t smem_u32(const void* p) {
    uint32_t a;
    asm("{ .reg .u64 t; cvta.to.shared.u64 t, %1; cvt.u32.u64 %0, t; }"
        : "=r"(a) : "l"(p));
    return a;
}
__device__ __forceinline__ void ldsm4(uint32_t* r, uint32_t addr) {
    asm volatile("ldmatrix.sync.aligned.m8n8.x4.shared.b16 {%0,%1,%2,%3}, [%4];"
        : "=r"(r[0]), "=r"(r[1]), "=r"(r[2]), "=r"(r[3]) : "r"(addr));
}
__device__ __forceinline__ void mma16816(float* d, const uint32_t* a, const uint32_t* b) {
    asm volatile("mma.sync.aligned.m16n8k16.row.col.f32.f16.f16.f32 "
        "{%0,%1,%2,%3}, {%4,%5,%6,%7}, {%8,%9}, {%0,%1,%2,%3};"
        : "+f"(d[0]), "+f"(d[1]), "+f"(d[2]), "+f"(d[3])
        : "r"(a[0]), "r"(a[1]), "r"(a[2]), "r"(a[3]), "r"(b[0]), "r"(b[1]));
}
__device__ __forceinline__ float tanha(float x) {
    float y;
    asm("tanh.approx.f32 %0, %1;" : "=f"(y) : "f"(x));
    return y;
}
__device__ __forceinline__ void cp16(uint32_t dst, const void* src) {
    asm volatile("cp.async.cg.shared.global [%0], [%1], 16;"
                 :: "r"(dst), "l"(src) : "memory");
}
#define CP_COMMIT() asm volatile("cp.async.commit_group;" ::: "memory")
#define CP_WAIT(n)  asm volatile("cp.async.wait_group %0;" :: "n"(n) : "memory")

// ---------------- Kernel 1: fused prep ----------------
__global__ __launch_bounds__(512)
void prep_kernel(const float* __restrict__ query,
                 const float* __restrict__ Wq,
                 const float* __restrict__ bq,
                 const float* __restrict__ Wk,
                 float* __restrict__ ctx) {
    const int blk = blockIdx.x;
    if (blk < 256) {
        __shared__ float tile[32][33];
        const int tv = blk & 15, th = blk >> 4;
        const int c  = threadIdx.x & 31;
        const int r0 = threadIdx.x >> 5;       // 0..15
        #pragma unroll
        for (int rr = 0; rr < 2; rr++) {
            int r = r0 + rr*16;
            tile[r][c] = Wk[(size_t)(tv*32 + r)*HD + th*32 + c];
        }
        __syncthreads();
        #pragma unroll
        for (int rr = 0; rr < 2; rr++) {
            int r2 = r0 + rr*16;
            g_WkT[(size_t)(th*32 + r2)*VD + tv*32 + c] =
                __float2half_rn(tile[c][r2]);
        }
    } else if (blk < 288) {
        int b = blk - 256;
        int h = threadIdx.x;
        __shared__ float qs[QD];
        qs[h] = query[b*QD + h];
        __syncthreads();
        float acc = 0.f;
        #pragma unroll 8
        for (int v = 0; v < QD; v++) acc += qs[v] * Wq[v*HD + h];
        g_qp[b*HD + h] = acc + bq[h];
    } else {
        ctx[(blk - 288)*512 + threadIdx.x] = 0.f;
    }
}

// ---------------- Kernel 2: mma.sync score GEMM (R12 configuration) ----------
#define APAD 520
#define OFF_A   0
#define OFF_B   133120
#define OFF_QP  199680
#define OFF_WO  201728
#define OFF_RED 203776
#define OFF_S0  204288
#define CHUNK_B 8192
#define SMEM_TOTAL (204288 + 3*CHUNK_B)

__device__ __forceinline__ void prefetch_b64(uint32_t bbase, int t, int tid) {
    const __half* src = g_WkT + (size_t)t * 64 * VD;
    #pragma unroll
    for (int it = 0; it < 16; it++) {
        int i = tid + it*256;
        int n = i >> 6;
        int g = i & 63;
        cp16(bbase + (uint32_t)(n*APAD + g*8)*2, src + (size_t)n*VD + g*8);
    }
}

__device__ __forceinline__ void issue_chunk(uint32_t sb, const float* vrow0,
                                            int c, int tid) {
    const float* src = vrow0 + c*16;
    #pragma unroll
    for (int j = 0; j < 2; j++) {
        int s = tid + j*256;          // 0..511 segments of 16B
        int r = s >> 2, p = s & 3;
        cp16(sb + (uint32_t)s*16, src + (size_t)r*VD + p*4);
    }
}

__device__ __forceinline__ void convert_chunk(const float* S, __half* As,
                                              int c, int tid) {
    #pragma unroll
    for (int j = 0; j < 2; j++) {
        int q = tid + j*256;          // float4 id 0..511
        int r = q >> 2, c4 = q & 3;
        float4 f = *(const float4*)(S + q*4);
        __half2 h0 = __floats2half2_rn(f.x, f.y);
        __half2 h1 = __floats2half2_rn(f.z, f.w);
        *(uint2*)(As + r*APAD + c*16 + c4*4) =
            make_uint2(*(uint32_t*)&h0, *(uint32_t*)&h1);
    }
}

// spill rows [t*16, t*16+16) of resident A (fp16) to g_Vh, streaming stores
__device__ __forceinline__ void spill_slab(const __half* As, __half* vh0,
                                           int t, int tid) {
    #pragma unroll
    for (int j = 0; j < 4; j++) {
        int q = tid + j*256;          // 0..1023
        int r = t*16 + (q >> 6);      // row
        int g = q & 63;               // uint4 within row
        uint4 u = *(const uint4*)(As + r*APAD + g*8);
        __stcs((uint4*)(vh0 + (size_t)r*VD + g*8), u);
    }
}

__device__ __forceinline__ void epilogue_tile(const float (&acc)[2][4][4], int t,
                                              int nw, int L,
                                              const float* qp_s, const float* wo_s,
                                              float* sp) {
    #pragma unroll
    for (int ni = 0; ni < 4; ni++) {
        const int hb = t*64 + nw*32 + ni*8 + 2*(L & 3);
        const float qp0 = qp_s[hb],   qp1 = qp_s[hb + 1];
        const float wo0 = wo_s[hb],   wo1 = wo_s[hb + 1];
        #pragma unroll
        for (int mi = 0; mi < 2; mi++) {
            float t0 = tanha(acc[mi][ni][0] + qp0);
            float t1 = tanha(acc[mi][ni][1] + qp1);
            float t2 = tanha(acc[mi][ni][2] + qp0);
            float t3 = tanha(acc[mi][ni][3] + qp1);
            sp[mi*2 + 0] += wo0*t0 + wo1*t1;
            sp[mi*2 + 1] += wo0*t2 + wo1*t3;
        }
    }
}

__global__ __launch_bounds__(256, 1)
void score_mma_kernel(const float* __restrict__ value,
                      const float* __restrict__ Wo,
                      const float* __restrict__ bo) {
    extern __shared__ char sm[];
    const uint32_t sbase = smem_u32(sm);
    const int tid = threadIdx.x;
    const int L   = tid & 31;
    const int wid = tid >> 5;
    const int mw  = wid & 3;
    const int nw  = wid >> 2;
    const int b   = blockIdx.x >> 5;
    const size_t row0 = (size_t)blockIdx.x * 128;

    __half* As  = (__half*)(sm + OFF_A);
    float* qp_s = (float*)(sm + OFF_QP);
    float* wo_s = (float*)(sm + OFF_WO);
    float* red  = (float*)(sm + OFF_RED);
    const float* vrow0 = value + row0 * VD;
    __half* vh0 = g_Vh + row0 * VD;

    prefetch_b64(sbase + OFF_B, 0, tid);
    CP_COMMIT();
    issue_chunk(sbase + OFF_S0 + 0*CHUNK_B, vrow0, 0, tid);
    CP_COMMIT();
    issue_chunk(sbase + OFF_S0 + 1*CHUNK_B, vrow0, 1, tid);
    CP_COMMIT();

    for (int i = tid; i < HD; i += 256) {
        qp_s[i] = g_qp[b*HD + i];
        wo_s[i] = Wo[i];
    }
    if (tid < 128) red[tid] = 0.f;

    const uint32_t aAddr = sbase + OFF_A +
        (uint32_t)(((mw*32 + (L & 15))*APAD + (L >> 4)*8) * 2);
    const uint32_t bAddr = sbase + OFF_B +
        (uint32_t)(((nw*32 + (L & 7) + ((L >> 4) << 3))*APAD + ((L >> 3) & 1)*8) * 2);

    float sp[4] = {0.f, 0.f, 0.f, 0.f};

    // ================= tile 0: chunked A pipeline =================
    float acc[2][4][4];
    #pragma unroll
    for (int mi = 0; mi < 2; mi++)
        #pragma unroll
        for (int ni = 0; ni < 4; ni++)
            #pragma unroll
            for (int j = 0; j < 4; j++) acc[mi][ni][j] = 0.f;

    for (int c = 0; c < 32; c++) {
        if (c <= 29) {
            int cn = c + 2;
            issue_chunk(sbase + OFF_S0 + (cn % 3)*CHUNK_B, vrow0, cn, tid);
            CP_COMMIT();
            CP_WAIT(2);
        } else if (c == 30) {
            CP_WAIT(1);
        } else {
            CP_WAIT(0);
        }
        __syncthreads();
        convert_chunk((const float*)(sm + OFF_S0 + (c % 3)*CHUNK_B), As, c, tid);
        __syncthreads();

        const uint32_t kb = (uint32_t)c * 32;
        uint32_t a0[4], a1[4], b0[4], b1[4];
        ldsm4(a0, aAddr + kb);
        ldsm4(a1, aAddr + 16*APAD*2 + kb);
        ldsm4(b0, bAddr + kb);
        ldsm4(b1, bAddr + 16*APAD*2 + kb);
        mma16816(acc[0][0], a0, b0 + 0);
        mma16816(acc[0][1], a0, b0 + 2);
        mma16816(acc[0][2], a0, b1 + 0);
        mma16816(acc[0][3], a0, b1 + 2);
        mma16816(acc[1][0], a1, b0 + 0);
        mma16816(acc[1][1], a1, b0 + 2);
        mma16816(acc[1][2], a1, b1 + 0);
        mma16816(acc[1][3], a1, b1 + 2);
    }

    __syncthreads();                  // all warps done reading B0
    prefetch_b64(sbase + OFF_B, 1, tid);
    CP_COMMIT();
    spill_slab(As, vh0, 0, tid);
    epilogue_tile(acc, 0, nw, L, qp_s, wo_s, sp);

    // ================= tiles 1..7: A resident, pipelined k-loop ===========
    for (int t = 1; t < 8; t++) {
        CP_WAIT(0);
        __syncthreads();

        #pragma unroll
        for (int mi = 0; mi < 2; mi++)
            #pragma unroll
            for (int ni = 0; ni < 4; ni++)
                #pragma unroll
                for (int j = 0; j < 4; j++) acc[mi][ni][j] = 0.f;

        uint32_t fA0[2][4], fA1[2][4], fB0[2][4], fB1[2][4];
        ldsm4(fA0[0], aAddr);
        ldsm4(fA1[0], aAddr + 16*APAD*2);
        ldsm4(fB0[0], bAddr);
        ldsm4(fB1[0], bAddr + 16*APAD*2);

        #pragma unroll
        for (int ks = 0; ks < 32; ks++) {
            const int cur = ks & 1, nxt = cur ^ 1;
            if (ks < 31) {
                const uint32_t kb = (uint32_t)(ks + 1) * 32;
                ldsm4(fA0[nxt], aAddr + kb);
                ldsm4(fA1[nxt], aAddr + 16*APAD*2 + kb);
                ldsm4(fB0[nxt], bAddr + kb);
                ldsm4(fB1[nxt], bAddr + 16*APAD*2 + kb);
            }
            mma16816(acc[0][0], fA0[cur], fB0[cur] + 0);
            mma16816(acc[0][1], fA0[cur], fB0[cur] + 2);
            mma16816(acc[0][2], fA0[cur], fB1[cur] + 0);
            mma16816(acc[0][3], fA0[cur], fB1[cur] + 2);
            mma16816(acc[1][0], fA1[cur], fB0[cur] + 0);
            mma16816(acc[1][1], fA1[cur], fB0[cur] + 2);
            mma16816(acc[1][2], fA1[cur], fB1[cur] + 0);
            mma16816(acc[1][3], fA1[cur], fB1[cur] + 2);
        }

        __syncthreads();
        if (t < 7) {
            prefetch_b64(sbase + OFF_B, t + 1, tid);
            CP_COMMIT();
        }
        spill_slab(As, vh0, t, tid);
        epilogue_tile(acc, t, nw, L, qp_s, wo_s, sp);
    }

    #pragma unroll
    for (int i = 0; i < 4; i++) {
        sp[i] += __shfl_xor_sync(0xffffffffu, sp[i], 1);
        sp[i] += __shfl_xor_sync(0xffffffffu, sp[i], 2);
    }
    if ((L & 3) == 0) {
        const int mr = mw*32 + (L >> 2);
        atomicAdd(&red[mr +  0], sp[0]);
        atomicAdd(&red[mr +  8], sp[1]);
        atomicAdd(&red[mr + 16], sp[2]);
        atomicAdd(&red[mr + 24], sp[3]);
    }
    __syncthreads();
    if (tid < 128)
        g_scores[row0 + tid] = red[tid] + bo[0];
}

// ---------------- Kernel 3: masked softmax, 1024 thr, 4 elems/thread ----------
__global__ __launch_bounds__(1024)
void softmax_kernel(const int* __restrict__ mask,
                    float* __restrict__ att_out) {
    const int b = blockIdx.x;
    const int tid = threadIdx.x;      // 1024
    const int L = tid & 31, w = tid >> 5;   // 32 warps
    __shared__ float sred[32];

    float v[4];
    float m = -3.0e38f;
    #pragma unroll
    for (int i = 0; i < 4; i++) {
        int s = tid + i*1024;
        float sc = (mask[b*SS + s] != 0) ? g_scores[b*SS + s] : -1e9f;
        v[i] = sc;
        m = fmaxf(m, sc);
    }
    #pragma unroll
    for (int off = 16; off > 0; off >>= 1)
        m = fmaxf(m, __shfl_xor_sync(0xffffffffu, m, off));
    if (L == 0) sred[w] = m;
    __syncthreads();
    if (w == 0) {
        float x = sred[L];
        #pragma unroll
        for (int off = 16; off > 0; off >>= 1)
            x = fmaxf(x, __shfl_xor_sync(0xffffffffu, x, off));
        if (L == 0) sred[0] = x;
    }
    __syncthreads();
    m = sred[0];
    __syncthreads();

    float sum = 0.f;
    #pragma unroll
    for (int i = 0; i < 4; i++) {
        v[i] = expf(v[i] - m);
        sum += v[i];
    }
    #pragma unroll
    for (int off = 16; off > 0; off >>= 1)
        sum += __shfl_xor_sync(0xffffffffu, sum, off);
    if (L == 0) sred[w] = sum;
    __syncthreads();
    if (w == 0) {
        float x = sred[L];
        #pragma unroll
        for (int off = 16; off > 0; off >>= 1)
            x += __shfl_xor_sync(0xffffffffu, x, off);
        if (L == 0) sred[0] = x;
    }
    __syncthreads();
    const float inv = 1.f / sred[0];

    #pragma unroll
    for (int i = 0; i < 4; i++)
        att_out[b*SS + tid + i*1024] = v[i] * inv;
}

// ---------------- Kernel 4: ctx from fp16 value (R12 layout, frozen) ----------
__global__ __launch_bounds__(128)
void ctx_part_kernel(const float* __restrict__ att,
                     float* __restrict__ ctx) {
    __shared__ float atts[SS / CSPLIT];          // 64
    const int b = blockIdx.y, sc = blockIdx.x, t = threadIdx.x;
    const int s0 = sc * (SS / CSPLIT);

    if (t < SS / CSPLIT) atts[t] = att[b*SS + s0 + t];
    __syncthreads();

    const __half* vb = g_Vh + ((size_t)(b*SS + s0))*VD + t*4;
    float ax = 0.f, ay = 0.f, az = 0.f, aw = 0.f;
    #pragma unroll 8
    for (int s = 0; s < SS / CSPLIT; s++) {
        float a = atts[s];
        uint2 u = *(const uint2*)(vb + (size_t)s*VD);
        float2 f01 = __half22float2(*(const __half2*)&u.x);
        float2 f23 = __half22float2(*(const __half2*)&u.y);
        ax = fmaf(a, f01.x, ax); ay = fmaf(a, f01.y, ay);
        az = fmaf(a, f23.x, az); aw = fmaf(a, f23.y, aw);
    }
    float* dst = ctx + b*VD + t*4;
    atomicAdd(dst + 0, ax);
    atomicAdd(dst + 1, ay);
    atomicAdd(dst + 2, az);
    atomicAdd(dst + 3, aw);
}

extern "C" void kernel_launch(void* const* d_in, const int* in_sizes, int n_in,
                              void* d_out, int out_size) {
    const float* query = (const float*)d_in[0];
    const float* value = (const float*)d_in[1];
    const int*   mask  = (const int*)d_in[2];   // bool promoted to int32
    const float* Wk    = (const float*)d_in[3];
    const float* Wq    = (const float*)d_in[4];
    const float* bq    = (const float*)d_in[5];
    const float* Wo    = (const float*)d_in[6];
    const float* bo    = (const float*)d_in[7];

    float* out = (float*)d_out;
    float* ctx = out;                 // [B, VD]
    float* att = out + CTX_SIZE;      // [B, S]

    prep_kernel<<<320, 512>>>(query, Wq, bq, Wk, ctx);

    cudaFuncSetAttribute(score_mma_kernel,
                         cudaFuncAttributeMaxDynamicSharedMemorySize, SMEM_TOTAL);
    score_mma_kernel<<<(BB*SS)/128, 256, SMEM_TOTAL>>>(value, Wo, bo);

    softmax_kernel<<<BB, 1024>>>(mask, att);

    ctx_part_kernel<<<dim3(CSPLIT, BB), 128>>>(att, ctx);
}